// round 2
// baseline (speedup 1.0000x reference)
#include <cuda_runtime.h>
#include <cstdint>
#include <cstddef>

#define H_    300000
#define CIN   16
#define COUT  32
#define KK    27
#define TB    128
#define NBLK  ((H_ + TB - 1) / TB)   // 2344
#define NIDX  (H_ * KK)              // 8,100,000

// Scratch (static device globals: allocation-free per harness rules)
__device__ float4 g_xT4[(size_t)H_ * 4];     // 19.2 MB: x transposed to [h][i], 16B-aligned
__device__ int    g_idx[NIDX];               // 32.4 MB: neigh normalized to int32
__device__ float  g_partials[64 * NBLK];     // rows 0..31 = sum(y), 32..63 = sum(y^2)
__device__ float  g_scale[COUT];
__device__ float  g_bias[COUT];
__device__ int    g_is64;

// ---------------------------------------------------------------------------
// Kernel 0: detect whether neigh buffer is int64 or int32.
// Sample odd 32-bit words (= high words if int64 little-endian). Values are
// random in [0,300000): for int32 data, 1024 samples all being 0/-1 is
// impossible in practice; for int64 data they are exactly 0 or -1.
// ---------------------------------------------------------------------------
__global__ void detect_kernel(const unsigned int* __restrict__ nv) {
    __shared__ int ok;
    if (threadIdx.x == 0) ok = 1;
    __syncthreads();
    // word index max = 1023*2000+1 < 2.05M < 8.1M words (int32 case lower bound)
    unsigned int v = nv[threadIdx.x * 2000 + 1];
    if (v != 0u && v != 0xFFFFFFFFu) ok = 0;   // benign race: only writes 0
    __syncthreads();
    if (threadIdx.x == 0) g_is64 = ok;
}

// ---------------------------------------------------------------------------
// Kernel 1: normalize neigh to int32 (coalesced).
// ---------------------------------------------------------------------------
__global__ void convert_neigh_kernel(const void* __restrict__ neigh) {
    int t = blockIdx.x * blockDim.x + threadIdx.x;
    if (t < NIDX) {
        int v;
        if (g_is64) {
            long long x = reinterpret_cast<const long long*>(neigh)[t];
            v = (x < 0) ? -1 : (int)x;
        } else {
            v = reinterpret_cast<const int*>(neigh)[t];
        }
        g_idx[t] = v;
    }
}

// ---------------------------------------------------------------------------
// Kernel 2: transpose x[i][h] -> xT[h][i] so each gather is one 64B row.
// ---------------------------------------------------------------------------
__global__ void transpose_x_kernel(const float* __restrict__ x) {
    int h = blockIdx.x * blockDim.x + threadIdx.x;
    if (h < H_) {
        float v[CIN];
#pragma unroll
        for (int i = 0; i < CIN; i++) v[i] = x[(size_t)i * H_ + h];
#pragma unroll
        for (int j = 0; j < 4; j++)
            g_xT4[(size_t)h * 4 + j] =
                make_float4(v[4 * j], v[4 * j + 1], v[4 * j + 2], v[4 * j + 3]);
    }
}

// ---------------------------------------------------------------------------
// Kernel 3: gather + conv + per-block BN partial sums.
// One thread per h. Weights in smem as ws[k][i][o] (uniform broadcast,
// o-contiguous -> LDS.128). Indices staged coalesced.
// ---------------------------------------------------------------------------
__global__ void __launch_bounds__(TB) conv_kernel(const float* __restrict__ w,
                                                  float* __restrict__ out) {
    extern __shared__ char smem[];
    float* ws   = reinterpret_cast<float*>(smem);                                     // 13824 f
    int*   sidx = reinterpret_cast<int*>(smem + KK * CIN * COUT * 4);                 // 3456 i
    float* red  = reinterpret_cast<float*>(smem + KK * CIN * COUT * 4 + TB * KK * 4); // 256 f

    const int tid = threadIdx.x;
    const int h0  = blockIdx.x * TB;

    // Stage weights: global w[o][i][k] -> smem ws[(k*16+i)*32+o]
    for (int t = tid; t < KK * CIN * COUT; t += TB) {
        int o = t / (CIN * KK);
        int r = t % (CIN * KK);
        int i = r / KK;
        int k = r % KK;
        ws[(k * CIN + i) * COUT + o] = w[t];
    }
    // Stage this block's 128*27 indices (coalesced int32 reads)
    for (int t = tid; t < TB * KK; t += TB) {
        int gi = h0 * KK + t;
        sidx[t] = (gi < NIDX) ? g_idx[gi] : -1;
    }
    __syncthreads();

    const int h = h0 + tid;
    float acc[COUT];
#pragma unroll
    for (int o = 0; o < COUT; o++) acc[o] = 0.f;

    if (h < H_) {
#pragma unroll 1   // keep k rolled: body fits I$; full unroll would blow it
        for (int k = 0; k < KK; k++) {
            int idx = sidx[tid * KK + k];   // stride 27 (odd) -> conflict-free
            float4 c0, c1, c2, c3;
            if (idx >= 0 && idx < H_) {
                const float4* p = g_xT4 + (size_t)idx * 4;
                c0 = p[0]; c1 = p[1]; c2 = p[2]; c3 = p[3];
            } else {
                c0 = c1 = c2 = c3 = make_float4(0.f, 0.f, 0.f, 0.f);
            }
            float c[CIN] = {c0.x, c0.y, c0.z, c0.w, c1.x, c1.y, c1.z, c1.w,
                            c2.x, c2.y, c2.z, c2.w, c3.x, c3.y, c3.z, c3.w};
            const float* wk = ws + k * CIN * COUT;
#pragma unroll
            for (int i = 0; i < CIN; i++) {
                float ci = c[i];
#pragma unroll
                for (int o = 0; o < COUT; o++)
                    acc[o] = fmaf(wk[i * COUT + o], ci, acc[o]);
            }
        }
#pragma unroll
        for (int o = 0; o < COUT; o++) out[(size_t)o * H_ + h] = acc[o];
    }

    // Deterministic BN partials: warp shuffle reduce, then cross-warp via smem.
    const int lane = tid & 31, wid = tid >> 5;
#pragma unroll 1
    for (int o = 0; o < COUT; o++) {
        float v = acc[o];
        float q = v * v;
#pragma unroll
        for (int s = 16; s > 0; s >>= 1) {
            v += __shfl_down_sync(0xffffffffu, v, s);
            q += __shfl_down_sync(0xffffffffu, q, s);
        }
        if (lane == 0) { red[wid * 64 + o * 2] = v; red[wid * 64 + o * 2 + 1] = q; }
    }
    __syncthreads();
    if (tid < 64) {
        int o   = (tid < 32) ? tid : (tid - 32);
        int off = (tid < 32) ? 0 : 1;
        float s = red[0 * 64 + o * 2 + off] + red[1 * 64 + o * 2 + off] +
                  red[2 * 64 + o * 2 + off] + red[3 * 64 + o * 2 + off];
        g_partials[tid * NBLK + blockIdx.x] = s;
    }
}

// ---------------------------------------------------------------------------
// Kernel 4: one block per channel; deterministic fp64 reduction of block
// partials -> fused scale/bias.
// ---------------------------------------------------------------------------
__global__ void stats_kernel(const float* __restrict__ gamma,
                             const float* __restrict__ beta) {
    const int o = blockIdx.x;
    double s1 = 0.0, s2 = 0.0;
    for (int b = threadIdx.x; b < NBLK; b += blockDim.x) {
        s1 += (double)g_partials[o * NBLK + b];
        s2 += (double)g_partials[(32 + o) * NBLK + b];
    }
    __shared__ double r1[256], r2[256];
    r1[threadIdx.x] = s1;
    r2[threadIdx.x] = s2;
    __syncthreads();
    for (int s = 128; s > 0; s >>= 1) {
        if (threadIdx.x < s) {
            r1[threadIdx.x] += r1[threadIdx.x + s];
            r2[threadIdx.x] += r2[threadIdx.x + s];
        }
        __syncthreads();
    }
    if (threadIdx.x == 0) {
        double mean = r1[0] / (double)H_;
        double var  = r2[0] / (double)H_ - mean * mean;
        float rstd  = rsqrtf((float)(var + 1e-5));
        float sc    = rstd * gamma[o];
        g_scale[o]  = sc;
        g_bias[o]   = beta[o] - (float)mean * sc;
    }
}

// ---------------------------------------------------------------------------
// Kernel 5: normalize in place (float4; H % 4 == 0, base 256B-aligned).
// ---------------------------------------------------------------------------
__global__ void bn_kernel(float* __restrict__ out) {
    const int o = blockIdx.y;
    const int t = blockIdx.x * blockDim.x + threadIdx.x;
    const float sc = g_scale[o], bi = g_bias[o];
    float4* p = reinterpret_cast<float4*>(out + (size_t)o * H_);
    if (t < H_ / 4) {
        float4 v = p[t];
        v.x = v.x * sc + bi;
        v.y = v.y * sc + bi;
        v.z = v.z * sc + bi;
        v.w = v.w * sc + bi;
        p[t] = v;
    }
}

// ---------------------------------------------------------------------------
extern "C" void kernel_launch(void* const* d_in, const int* in_sizes, int n_in,
                              void* d_out, int out_size) {
    const float* x     = (const float*)d_in[0];  // (1,16,300000,1)
    const float* w     = (const float*)d_in[1];  // (32,16,27)
    const float* gamma = (const float*)d_in[2];  // (32,)
    const float* beta  = (const float*)d_in[3];  // (32,)
    const void*  neigh = d_in[4];                // (300000,27) int64 OR int32
    float*       out   = (float*)d_out;          // (1,32,300000,1)

    const int smem_bytes = KK * CIN * COUT * 4 + TB * KK * 4 + 4 * 64 * 4; // 70144
    cudaFuncSetAttribute(conv_kernel, cudaFuncAttributeMaxDynamicSharedMemorySize,
                         smem_bytes);

    detect_kernel<<<1, 1024>>>((const unsigned int*)neigh);
    convert_neigh_kernel<<<(NIDX + 255) / 256, 256>>>(neigh);
    transpose_x_kernel<<<(H_ + 255) / 256, 256>>>(x);
    conv_kernel<<<NBLK, TB, smem_bytes>>>(w, out);
    stats_kernel<<<COUT, 256>>>(gamma, beta);
    bn_kernel<<<dim3((H_ / 4 + 255) / 256, COUT), 256>>>(out);
}

// round 3
// speedup vs baseline: 1.3182x; 1.3182x over previous
#include <cuda_runtime.h>
#include <cstdint>
#include <cstddef>

#define H_    300000
#define CIN   16
#define COUT  32
#define KK    27
#define TB    128
#define NBLK  ((H_ + TB - 1) / TB)   // 2344
#define NIDX  (H_ * KK)              // 8,100,000
#define PITCH 132                    // col row pitch in floats (128 + 4 pad, 16B-aligned)
#define COLSZ (CIN * PITCH)          // floats per col buffer

// Scratch (static device globals: allocation-free per harness rules)
__device__ float4 g_xT4[(size_t)H_ * 4];     // 19.2 MB: x transposed to [h][i], 16B-aligned
__device__ float  g_partials[64 * NBLK];     // rows 0..31 = sum(y), 32..63 = sum(y^2)
__device__ float  g_scale[COUT];
__device__ float  g_bias[COUT];
__device__ int    g_is64;

// packed f32x2 helpers (sm_103a FFMA2 path — only reachable via PTX)
__device__ __forceinline__ unsigned long long fma_f32x2(unsigned long long a,
                                                        unsigned long long b,
                                                        unsigned long long c) {
    unsigned long long d;
    asm("fma.rn.f32x2 %0, %1, %2, %3;" : "=l"(d) : "l"(a), "l"(b), "l"(c));
    return d;
}
__device__ __forceinline__ unsigned long long pack_dup(float v) {
    unsigned long long d;
    unsigned int u = __float_as_uint(v);
    asm("mov.b64 %0, {%1, %2};" : "=l"(d) : "r"(u), "r"(u));
    return d;
}
__device__ __forceinline__ void unpack2(unsigned long long p, float& lo, float& hi) {
    unsigned int a, b;
    asm("mov.b64 {%0, %1}, %2;" : "=r"(a), "=r"(b) : "l"(p));
    lo = __uint_as_float(a);
    hi = __uint_as_float(b);
}

// ---------------------------------------------------------------------------
// Kernel 0: detect whether neigh buffer is int64 or int32 (JAX x64 off => i32).
// Sample odd 32-bit words (high words if int64 LE): int64 -> all 0/-1.
// ---------------------------------------------------------------------------
__global__ void detect_kernel(const unsigned int* __restrict__ nv) {
    __shared__ int ok;
    if (threadIdx.x == 0) ok = 1;
    __syncthreads();
    unsigned int v = nv[threadIdx.x * 2000 + 1];   // max idx 2.05M < 8.1M words
    if (v != 0u && v != 0xFFFFFFFFu) ok = 0;       // benign race: only writes 0
    __syncthreads();
    if (threadIdx.x == 0) g_is64 = ok;
}

// ---------------------------------------------------------------------------
// Kernel 1: transpose x[i][h] -> xT[h][i] so each gather row is one 64B line.
// ---------------------------------------------------------------------------
__global__ void transpose_x_kernel(const float* __restrict__ x) {
    int h = blockIdx.x * blockDim.x + threadIdx.x;
    if (h < H_) {
        float v[CIN];
#pragma unroll
        for (int i = 0; i < CIN; i++) v[i] = x[(size_t)i * H_ + h];
#pragma unroll
        for (int j = 0; j < 4; j++)
            g_xT4[(size_t)h * 4 + j] =
                make_float4(v[4 * j], v[4 * j + 1], v[4 * j + 2], v[4 * j + 3]);
    }
}

// ---------------------------------------------------------------------------
// Kernel 2: register-blocked GEMM y[32,128] = W[32,16*27] * col[16*27,128]
// per block, k-tiled with double-buffered cooperative gather + FFMA2.
// Thread tile: 8 outputs (warp-owned) x 4 h. BN partials via warp shuffles.
// ---------------------------------------------------------------------------
__global__ void __launch_bounds__(TB) conv_kernel(const float* __restrict__ w,
                                                  const void* __restrict__ neigh,
                                                  float* __restrict__ out) {
    extern __shared__ char smem[];
    float* ws   = reinterpret_cast<float*>(smem);                          // 13824 f
    int*   sidx = reinterpret_cast<int*>(smem + 13824 * 4);                // 3456 i
    float* col  = reinterpret_cast<float*>(smem + 13824 * 4 + 3456 * 4);   // 2*COLSZ f

    const int tid  = threadIdx.x;
    const int lane = tid & 31;
    const int wid  = tid >> 5;       // warp id = output group
    const int h0   = blockIdx.x * TB;
    const int og   = wid * 8;        // this warp's 8 output channels
    const int hg   = lane * 4;       // this thread's 4 h (contiguous)

    // Stage weights: global w[o][i][k] -> smem ws[(k*16+i)*32+o]
    for (int t = tid; t < KK * CIN * COUT; t += TB) {
        int o = t / (CIN * KK);
        int r = t % (CIN * KK);
        int i = r / KK;
        int k = r % KK;
        ws[(k * CIN + i) * COUT + o] = w[t];
    }
    // Stage indices for this block's 128 rows (coalesced; dtype-normalized)
    {
        const int is64 = g_is64;
        for (int t = tid; t < TB * KK; t += TB) {
            long long gi = (long long)h0 * KK + t;
            int v = -1;
            if (gi < (long long)NIDX) {
                if (is64) {
                    long long x = reinterpret_cast<const long long*>(neigh)[gi];
                    v = (x < 0 || x >= H_) ? -1 : (int)x;
                } else {
                    int x = reinterpret_cast<const int*>(neigh)[gi];
                    v = (x < 0 || x >= H_) ? -1 : x;
                }
            }
            sidx[t] = v;
        }
    }

    // Cooperative gather of col tile for step k into buffer buf.
    // 4 lanes fetch the 4 float4's of one xT row -> 1 wavefront / 64B row.
    const int q     = tid & 3;       // which float4 of the row
    const int rbase = tid >> 2;      // row within block (0..31), step 32
    auto gather = [&](int k, float* dst) {
#pragma unroll
        for (int j = 0; j < 4; j++) {
            int r   = rbase + 32 * j;
            int idx = sidx[r * KK + k];
            float4 v = make_float4(0.f, 0.f, 0.f, 0.f);
            if (idx >= 0) v = g_xT4[(size_t)idx * 4 + q];
            float* p = dst + (4 * q) * PITCH + r;
            p[0 * PITCH] = v.x;
            p[1 * PITCH] = v.y;
            p[2 * PITCH] = v.z;
            p[3 * PITCH] = v.w;
        }
    };

    __syncthreads();
    gather(0, col);
    __syncthreads();

    unsigned long long acc[4][4];    // [o-pair][h] packed (og+2op, og+2op+1)
#pragma unroll
    for (int a = 0; a < 4; a++)
#pragma unroll
        for (int b = 0; b < 4; b++) acc[a][b] = 0ull;

#pragma unroll 1
    for (int k = 0; k < KK; k++) {
        const float* cc = col + (k & 1) * COLSZ;
        float*       cn = col + ((k + 1) & 1) * COLSZ;
        if (k + 1 < KK) gather(k + 1, cn);   // prefetch next tile (other buffer)

#pragma unroll
        for (int i = 0; i < CIN; i++) {
            // 4 h values for this thread (16B-aligned: PITCH%4==0, hg%4==0)
            float4 c4 = *reinterpret_cast<const float4*>(cc + i * PITCH + hg);
            unsigned long long cd[4] = {pack_dup(c4.x), pack_dup(c4.y),
                                        pack_dup(c4.z), pack_dup(c4.w)};
            // 8 weights = 4 natural (o,o+1) pairs, broadcast LDS.128
            const unsigned long long* wp =
                reinterpret_cast<const unsigned long long*>(ws + (k * CIN + i) * COUT + og);
            unsigned long long w01 = wp[0], w23 = wp[1], w45 = wp[2], w67 = wp[3];
#pragma unroll
            for (int hh = 0; hh < 4; hh++) {
                acc[0][hh] = fma_f32x2(w01, cd[hh], acc[0][hh]);
                acc[1][hh] = fma_f32x2(w23, cd[hh], acc[1][hh]);
                acc[2][hh] = fma_f32x2(w45, cd[hh], acc[2][hh]);
                acc[3][hh] = fma_f32x2(w67, cd[hh], acc[3][hh]);
            }
        }
        __syncthreads();
    }

    // Unpack, write y (coalesced float4 per o), accumulate BN partials.
    const bool valid = (h0 + hg) < H_;   // quad-granular: H_ % 4 == 0
    float s[8], ss[8];
#pragma unroll
    for (int op = 0; op < 4; op++) {
        float lo[4], hi[4];
#pragma unroll
        for (int hh = 0; hh < 4; hh++) unpack2(acc[op][hh], lo[hh], hi[hh]);
        if (valid) {
            *reinterpret_cast<float4*>(out + (size_t)(og + 2 * op) * H_ + h0 + hg) =
                make_float4(lo[0], lo[1], lo[2], lo[3]);
            *reinterpret_cast<float4*>(out + (size_t)(og + 2 * op + 1) * H_ + h0 + hg) =
                make_float4(hi[0], hi[1], hi[2], hi[3]);
        }
        s[2 * op]      = lo[0] + lo[1] + lo[2] + lo[3];
        s[2 * op + 1]  = hi[0] + hi[1] + hi[2] + hi[3];
        ss[2 * op]     = lo[0] * lo[0] + lo[1] * lo[1] + lo[2] * lo[2] + lo[3] * lo[3];
        ss[2 * op + 1] = hi[0] * hi[0] + hi[1] * hi[1] + hi[2] * hi[2] + hi[3] * hi[3];
    }
#pragma unroll
    for (int oo = 0; oo < 8; oo++) {
        float v = s[oo], qv = ss[oo];
#pragma unroll
        for (int sft = 16; sft > 0; sft >>= 1) {
            v  += __shfl_down_sync(0xffffffffu, v, sft);
            qv += __shfl_down_sync(0xffffffffu, qv, sft);
        }
        if (lane == 0) {
            g_partials[(og + oo) * NBLK + blockIdx.x]      = v;
            g_partials[(32 + og + oo) * NBLK + blockIdx.x] = qv;
        }
    }
}

// ---------------------------------------------------------------------------
// Kernel 3: one block per channel; deterministic fp64 reduction -> scale/bias.
// ---------------------------------------------------------------------------
__global__ void stats_kernel(const float* __restrict__ gamma,
                             const float* __restrict__ beta) {
    const int o = blockIdx.x;
    double s1 = 0.0, s2 = 0.0;
    for (int b = threadIdx.x; b < NBLK; b += blockDim.x) {
        s1 += (double)g_partials[o * NBLK + b];
        s2 += (double)g_partials[(32 + o) * NBLK + b];
    }
    __shared__ double r1[256], r2[256];
    r1[threadIdx.x] = s1;
    r2[threadIdx.x] = s2;
    __syncthreads();
    for (int sft = 128; sft > 0; sft >>= 1) {
        if (threadIdx.x < sft) {
            r1[threadIdx.x] += r1[threadIdx.x + sft];
            r2[threadIdx.x] += r2[threadIdx.x + sft];
        }
        __syncthreads();
    }
    if (threadIdx.x == 0) {
        double mean = r1[0] / (double)H_;
        double var  = r2[0] / (double)H_ - mean * mean;
        float rstd  = rsqrtf((float)(var + 1e-5));
        float sc    = rstd * gamma[o];
        g_scale[o]  = sc;
        g_bias[o]   = beta[o] - (float)mean * sc;
    }
}

// ---------------------------------------------------------------------------
// Kernel 4: normalize in place (float4; H % 4 == 0).
// ---------------------------------------------------------------------------
__global__ void bn_kernel(float* __restrict__ out) {
    const int o = blockIdx.y;
    const int t = blockIdx.x * blockDim.x + threadIdx.x;
    const float sc = g_scale[o], bi = g_bias[o];
    float4* p = reinterpret_cast<float4*>(out + (size_t)o * H_);
    if (t < H_ / 4) {
        float4 v = p[t];
        v.x = v.x * sc + bi;
        v.y = v.y * sc + bi;
        v.z = v.z * sc + bi;
        v.w = v.w * sc + bi;
        p[t] = v;
    }
}

// ---------------------------------------------------------------------------
extern "C" void kernel_launch(void* const* d_in, const int* in_sizes, int n_in,
                              void* d_out, int out_size) {
    const float* x     = (const float*)d_in[0];  // (1,16,300000,1)
    const float* w     = (const float*)d_in[1];  // (32,16,27)
    const float* gamma = (const float*)d_in[2];  // (32,)
    const float* beta  = (const float*)d_in[3];  // (32,)
    const void*  neigh = d_in[4];                // (300000,27) int64 or int32
    float*       out   = (float*)d_out;          // (1,32,300000,1)

    const int smem_bytes = 13824 * 4 + 3456 * 4 + 2 * COLSZ * 4;  // 85,992 B
    cudaFuncSetAttribute(conv_kernel, cudaFuncAttributeMaxDynamicSharedMemorySize,
                         smem_bytes);

    detect_kernel<<<1, 1024>>>((const unsigned int*)neigh);
    transpose_x_kernel<<<(H_ + 255) / 256, 256>>>(x);
    conv_kernel<<<NBLK, TB, smem_bytes>>>(w, neigh, out);
    stats_kernel<<<COUT, 256>>>(gamma, beta);
    bn_kernel<<<dim3((H_ / 4 + 255) / 256, COUT), 256>>>(out);
}

// round 4
// speedup vs baseline: 2.0912x; 1.5864x over previous
#include <cuda_runtime.h>
#include <cstdint>
#include <cstddef>

#define H_    300000
#define CIN   16
#define COUT  32
#define KK    27
#define HB    256                     // h per block
#define TB    256                     // threads per block
#define NBLK  ((H_ + HB - 1) / HB)    // 1172
#define NPART (NBLK * 2)              // partials per channel (2 h-halves/block)
#define NIDX  (H_ * KK)               // 8,100,000
#define PITCH (HB + 4)                // 260: col row pitch (16B-aligned, odd/32 stride-ish)
#define COLSZ (CIN * PITCH)           // floats per col buffer
#define WSZ   (KK * CIN * COUT)       // 13824 weight floats

// Scratch (static device globals: allocation-free per harness rules)
__device__ float4 g_xT4[(size_t)H_ * 4];      // 19.2 MB: x transposed to [h][i]
__device__ float  g_partials[64 * NPART];     // rows 0..31 sum(y), 32..63 sum(y^2)
__device__ float  g_scale[COUT];
__device__ float  g_bias[COUT];
__device__ int    g_is64;

// packed f32x2 helpers (sm_103a FFMA2 — only reachable via PTX)
__device__ __forceinline__ unsigned long long fma_f32x2(unsigned long long a,
                                                        unsigned long long b,
                                                        unsigned long long c) {
    unsigned long long d;
    asm("fma.rn.f32x2 %0, %1, %2, %3;" : "=l"(d) : "l"(a), "l"(b), "l"(c));
    return d;
}
__device__ __forceinline__ unsigned long long pack_dup(float v) {
    unsigned long long d;
    unsigned int u = __float_as_uint(v);
    asm("mov.b64 %0, {%1, %2};" : "=l"(d) : "r"(u), "r"(u));
    return d;
}
__device__ __forceinline__ void unpack2(unsigned long long p, float& lo, float& hi) {
    unsigned int a, b;
    asm("mov.b64 {%0, %1}, %2;" : "=r"(a), "=r"(b) : "l"(p));
    lo = __uint_as_float(a);
    hi = __uint_as_float(b);
}

// ---------------------------------------------------------------------------
// Kernel 0: detect int64 vs int32 neigh (JAX x64 off => i32). Sample odd words.
// ---------------------------------------------------------------------------
__global__ void detect_kernel(const unsigned int* __restrict__ nv) {
    __shared__ int ok;
    if (threadIdx.x == 0) ok = 1;
    __syncthreads();
    unsigned int v = nv[threadIdx.x * 2000 + 1];   // max idx < 2.05M < 8.1M words
    if (v != 0u && v != 0xFFFFFFFFu) ok = 0;       // benign race: only writes 0
    __syncthreads();
    if (threadIdx.x == 0) g_is64 = ok;
}

// ---------------------------------------------------------------------------
// Kernel 1: transpose x[i][h] -> xT[h][i]; each gather row becomes one 64B line.
// ---------------------------------------------------------------------------
__global__ void transpose_x_kernel(const float* __restrict__ x) {
    int h = blockIdx.x * blockDim.x + threadIdx.x;
    if (h < H_) {
        float v[CIN];
#pragma unroll
        for (int i = 0; i < CIN; i++) v[i] = x[(size_t)i * H_ + h];
#pragma unroll
        for (int j = 0; j < 4; j++)
            g_xT4[(size_t)h * 4 + j] =
                make_float4(v[4 * j], v[4 * j + 1], v[4 * j + 2], v[4 * j + 3]);
    }
}

// ---------------------------------------------------------------------------
// Kernel 2: register-blocked GEMM y[32,256] = W[32,432] * col[432,256] per
// block, k-tiled, double-buffered cooperative gather, FFMA2 math.
// 8 warps: warp = (o-group 0..3) x (h-half 0..1). Thread tile 8o x 4h.
// Indices read directly from neigh (L1-resident per block, ~28KB footprint).
// ---------------------------------------------------------------------------
__global__ void __launch_bounds__(TB, 2) conv_kernel(const float* __restrict__ w,
                                                     const int* __restrict__ neigh32,
                                                     float* __restrict__ out) {
    extern __shared__ float smem[];
    float* ws  = smem;           // 13824 floats
    float* col = smem + WSZ;     // 2 * COLSZ floats

    const int tid  = threadIdx.x;
    const int lane = tid & 31;
    const int wid  = tid >> 5;            // 0..7
    const int h0   = blockIdx.x * HB;
    const int og   = (wid & 3) * 8;       // warp's 8 output channels
    const int half = wid >> 2;            // h-half 0/1
    const int hg   = half * 128 + lane * 4;

    // Stage weights: w[o][i][k] -> ws[(k*16+i)*32+o]
    for (int t = tid; t < WSZ; t += TB) {
        int o = t / (CIN * KK);
        int r = t % (CIN * KK);
        int i = r / KK;
        int k = r % KK;
        ws[(k * CIN + i) * COUT + o] = w[t];
    }

    const int is64  = g_is64;
    const int q     = tid & 3;       // which float4 of a gathered row
    const int rbase = tid >> 2;      // 0..63; rows r = rbase + 64j

    // Cooperative gather of col tile for step k: 4 lanes fetch one 64B row.
    auto gather = [&](int k, float* dst) {
#pragma unroll
        for (int j = 0; j < 4; j++) {
            int r = rbase + 64 * j;
            int h = h0 + r;
            int idx = -1;
            if (h < H_) {
                long long gi = (long long)h * KK + k;
                idx = neigh32[is64 ? 2 * gi : gi];   // low word: sign-safe
            }
            float4 v = make_float4(0.f, 0.f, 0.f, 0.f);
            if (idx >= 0 && idx < H_) v = g_xT4[(size_t)idx * 4 + q];
            float* p = dst + (4 * q) * PITCH + r;
            p[0 * PITCH] = v.x;
            p[1 * PITCH] = v.y;
            p[2 * PITCH] = v.z;
            p[3 * PITCH] = v.w;
        }
    };

    __syncthreads();          // weights staged
    gather(0, col);
    __syncthreads();

    unsigned long long acc[4][4];   // [o-pair][h]
#pragma unroll
    for (int a = 0; a < 4; a++)
#pragma unroll
        for (int b = 0; b < 4; b++) acc[a][b] = 0ull;

#pragma unroll 1
    for (int k = 0; k < KK; k++) {
        const float* cc = col + (k & 1) * COLSZ;
        float*       cn = col + ((k + 1) & 1) * COLSZ;
        if (k + 1 < KK) gather(k + 1, cn);

#pragma unroll
        for (int i = 0; i < CIN; i++) {
            float4 c4 = *reinterpret_cast<const float4*>(cc + i * PITCH + hg);
            unsigned long long cd[4] = {pack_dup(c4.x), pack_dup(c4.y),
                                        pack_dup(c4.z), pack_dup(c4.w)};
            const unsigned long long* wp =
                reinterpret_cast<const unsigned long long*>(ws + (k * CIN + i) * COUT + og);
            unsigned long long w01 = wp[0], w23 = wp[1], w45 = wp[2], w67 = wp[3];
#pragma unroll
            for (int hh = 0; hh < 4; hh++) {
                acc[0][hh] = fma_f32x2(w01, cd[hh], acc[0][hh]);
                acc[1][hh] = fma_f32x2(w23, cd[hh], acc[1][hh]);
                acc[2][hh] = fma_f32x2(w45, cd[hh], acc[2][hh]);
                acc[3][hh] = fma_f32x2(w67, cd[hh], acc[3][hh]);
            }
        }
        __syncthreads();
    }

    // Unpack, write y (coalesced float4 per o), per-warp BN partials.
    const bool valid = (h0 + hg) < H_;   // quad-granular: H_ % 4 == 0
    float s[8], ss[8];
#pragma unroll
    for (int op = 0; op < 4; op++) {
        float lo[4], hi[4];
#pragma unroll
        for (int hh = 0; hh < 4; hh++) unpack2(acc[op][hh], lo[hh], hi[hh]);
        if (valid) {
            *reinterpret_cast<float4*>(out + (size_t)(og + 2 * op) * H_ + h0 + hg) =
                make_float4(lo[0], lo[1], lo[2], lo[3]);
            *reinterpret_cast<float4*>(out + (size_t)(og + 2 * op + 1) * H_ + h0 + hg) =
                make_float4(hi[0], hi[1], hi[2], hi[3]);
        }
        s[2 * op]      = lo[0] + lo[1] + lo[2] + lo[3];
        s[2 * op + 1]  = hi[0] + hi[1] + hi[2] + hi[3];
        ss[2 * op]     = lo[0] * lo[0] + lo[1] * lo[1] + lo[2] * lo[2] + lo[3] * lo[3];
        ss[2 * op + 1] = hi[0] * hi[0] + hi[1] * hi[1] + hi[2] * hi[2] + hi[3] * hi[3];
    }
    const int pidx = blockIdx.x * 2 + half;
#pragma unroll
    for (int oo = 0; oo < 8; oo++) {
        float v = s[oo], qv = ss[oo];
#pragma unroll
        for (int sft = 16; sft > 0; sft >>= 1) {
            v  += __shfl_down_sync(0xffffffffu, v, sft);
            qv += __shfl_down_sync(0xffffffffu, qv, sft);
        }
        if (lane == 0) {
            g_partials[(og + oo) * NPART + pidx]      = v;
            g_partials[(32 + og + oo) * NPART + pidx] = qv;
        }
    }
}

// ---------------------------------------------------------------------------
// Kernel 3: one block per channel; deterministic fp64 reduction -> scale/bias.
// ---------------------------------------------------------------------------
__global__ void stats_kernel(const float* __restrict__ gamma,
                             const float* __restrict__ beta) {
    const int o = blockIdx.x;
    double s1 = 0.0, s2 = 0.0;
    for (int b = threadIdx.x; b < NPART; b += blockDim.x) {
        s1 += (double)g_partials[o * NPART + b];
        s2 += (double)g_partials[(32 + o) * NPART + b];
    }
    __shared__ double r1[256], r2[256];
    r1[threadIdx.x] = s1;
    r2[threadIdx.x] = s2;
    __syncthreads();
    for (int sft = 128; sft > 0; sft >>= 1) {
        if (threadIdx.x < sft) {
            r1[threadIdx.x] += r1[threadIdx.x + sft];
            r2[threadIdx.x] += r2[threadIdx.x + sft];
        }
        __syncthreads();
    }
    if (threadIdx.x == 0) {
        double mean = r1[0] / (double)H_;
        double var  = r2[0] / (double)H_ - mean * mean;
        float rstd  = rsqrtf((float)(var + 1e-5));
        float sc    = rstd * gamma[o];
        g_scale[o]  = sc;
        g_bias[o]   = beta[o] - (float)mean * sc;
    }
}

// ---------------------------------------------------------------------------
// Kernel 4: normalize in place (float4; H % 4 == 0).
// ---------------------------------------------------------------------------
__global__ void bn_kernel(float* __restrict__ out) {
    const int o = blockIdx.y;
    const int t = blockIdx.x * blockDim.x + threadIdx.x;
    const float sc = g_scale[o], bi = g_bias[o];
    float4* p = reinterpret_cast<float4*>(out + (size_t)o * H_);
    if (t < H_ / 4) {
        float4 v = p[t];
        v.x = v.x * sc + bi;
        v.y = v.y * sc + bi;
        v.z = v.z * sc + bi;
        v.w = v.w * sc + bi;
        p[t] = v;
    }
}

// ---------------------------------------------------------------------------
extern "C" void kernel_launch(void* const* d_in, const int* in_sizes, int n_in,
                              void* d_out, int out_size) {
    const float* x     = (const float*)d_in[0];  // (1,16,300000,1)
    const float* w     = (const float*)d_in[1];  // (32,16,27)
    const float* gamma = (const float*)d_in[2];  // (32,)
    const float* beta  = (const float*)d_in[3];  // (32,)
    const void*  neigh = d_in[4];                // (300000,27) i64 or i32
    float*       out   = (float*)d_out;          // (1,32,300000,1)

    const int smem_bytes = (WSZ + 2 * COLSZ) * 4;   // 55296 + 33280 = 88576 B
    cudaFuncSetAttribute(conv_kernel, cudaFuncAttributeMaxDynamicSharedMemorySize,
                         smem_bytes);

    detect_kernel<<<1, 1024>>>((const unsigned int*)neigh);
    transpose_x_kernel<<<(H_ + 255) / 256, 256>>>(x);
    conv_kernel<<<NBLK, TB, smem_bytes>>>(w, (const int*)neigh, out);
    stats_kernel<<<COUT, 256>>>(gamma, beta);
    bn_kernel<<<dim3((H_ / 4 + 255) / 256, COUT), 256>>>(out);
}

// round 5
// speedup vs baseline: 2.1571x; 1.0315x over previous
#include <cuda_runtime.h>
#include <cstdint>
#include <cstddef>

#define H_    300000
#define CIN   16
#define COUT  32
#define KK    27
#define HB    128                     // h per block
#define TB    128                     // threads per block
#define NBLK  ((H_ + HB - 1) / HB)    // 2344
#define NIDX  (H_ * KK)               // 8,100,000
#define PITCH (HB + 4)                // 132: col row pitch (16B-aligned)
#define COLSZ (CIN * PITCH)           // floats per col buffer
#define WSZ   (KK * CIN * COUT)       // 13824 weight floats

// Scratch (static device globals: allocation-free per harness rules)
__device__ float4 g_xT4[(size_t)H_ * 4];     // 19.2 MB: x transposed to [h][i]
__device__ float  g_wpk[WSZ];                // 55 KB: weights repacked [(k*16+i)*32+o]
__device__ float  g_partials[64 * NBLK];     // rows 0..31 sum(y), 32..63 sum(y^2)
__device__ float  g_scale[COUT];
__device__ float  g_bias[COUT];
__device__ int    g_is64;

// packed f32x2 helpers (sm_103a FFMA2 — only reachable via PTX)
__device__ __forceinline__ unsigned long long fma_f32x2(unsigned long long a,
                                                        unsigned long long b,
                                                        unsigned long long c) {
    unsigned long long d;
    asm("fma.rn.f32x2 %0, %1, %2, %3;" : "=l"(d) : "l"(a), "l"(b), "l"(c));
    return d;
}
__device__ __forceinline__ unsigned long long pack_dup(float v) {
    unsigned long long d;
    unsigned int u = __float_as_uint(v);
    asm("mov.b64 %0, {%1, %2};" : "=l"(d) : "r"(u), "r"(u));
    return d;
}
__device__ __forceinline__ void unpack2(unsigned long long p, float& lo, float& hi) {
    unsigned int a, b;
    asm("mov.b64 {%0, %1}, %2;" : "=r"(a), "=r"(b) : "l"(p));
    lo = __uint_as_float(a);
    hi = __uint_as_float(b);
}
__device__ __forceinline__ unsigned long long pack2(float lo, float hi) {
    unsigned long long d;
    asm("mov.b64 %0, {%1, %2};" : "=l"(d) : "r"(__float_as_uint(lo)), "r"(__float_as_uint(hi)));
    return d;
}

// ---------------------------------------------------------------------------
// Kernel 0: detect int64 vs int32 neigh (JAX x64 off => i32). Sample odd words.
// ---------------------------------------------------------------------------
__global__ void detect_kernel(const unsigned int* __restrict__ nv) {
    __shared__ int ok;
    if (threadIdx.x == 0) ok = 1;
    __syncthreads();
    unsigned int v = nv[threadIdx.x * 2000 + 1];   // max idx < 2.05M < 8.1M words
    if (v != 0u && v != 0xFFFFFFFFu) ok = 0;       // benign race: only writes 0
    __syncthreads();
    if (threadIdx.x == 0) g_is64 = ok;
}

// ---------------------------------------------------------------------------
// Kernel 1: repack weights w[o][i][k] -> g_wpk[(k*16+i)*32+o] (o-contiguous).
// ---------------------------------------------------------------------------
__global__ void repack_w_kernel(const float* __restrict__ w) {
    int t = blockIdx.x * blockDim.x + threadIdx.x;
    if (t < WSZ) {
        int o = t / (CIN * KK);
        int r = t % (CIN * KK);
        int i = r / KK;
        int k = r % KK;
        g_wpk[(k * CIN + i) * COUT + o] = w[t];
    }
}

// ---------------------------------------------------------------------------
// Kernel 2: transpose x[i][h] -> xT[h][i]; each gather row becomes one 64B line.
// ---------------------------------------------------------------------------
__global__ void transpose_x_kernel(const float* __restrict__ x) {
    int h = blockIdx.x * blockDim.x + threadIdx.x;
    if (h < H_) {
        float v[CIN];
#pragma unroll
        for (int i = 0; i < CIN; i++) v[i] = x[(size_t)i * H_ + h];
#pragma unroll
        for (int j = 0; j < 4; j++)
            g_xT4[(size_t)h * 4 + j] =
                make_float4(v[4 * j], v[4 * j + 1], v[4 * j + 2], v[4 * j + 3]);
    }
}

// ---------------------------------------------------------------------------
// Kernel 3: register-blocked GEMM y[32,128] = W[32,432] * col[432,128] per
// block. Double-buffered cooperative gather; FFMA2 math; weights via uniform
// __ldg (L1-resident broadcast). Small smem (16.9 KB) -> ~7 CTAs/SM.
// 4 warps: warp = o-group. Thread tile 8o x 4h.
// ---------------------------------------------------------------------------
__global__ void __launch_bounds__(TB, 6) conv_kernel(const int* __restrict__ neigh32,
                                                     float* __restrict__ out) {
    __shared__ float col[2 * COLSZ];   // 16896 B

    const int tid  = threadIdx.x;
    const int lane = tid & 31;
    const int wid  = tid >> 5;        // 0..3 = o-group
    const int h0   = blockIdx.x * HB;
    const int og   = wid * 8;         // warp's 8 output channels
    const int hg   = lane * 4;        // thread's 4 h (contiguous)

    const int is64  = g_is64;
    const int q     = tid & 3;        // which float4 of a gathered row
    const int rbase = tid >> 2;       // 0..31; rows r = rbase + 32j

    // Cooperative gather of col tile for step k: 4 lanes fetch one 64B row.
    auto gather = [&](int k, float* dst) {
#pragma unroll
        for (int j = 0; j < 4; j++) {
            int r = rbase + 32 * j;
            int h = h0 + r;
            int idx = -1;
            if (h < H_) {
                int gi = h * KK + k;              // <= 8.1M, fits int
                idx = neigh32[is64 ? 2 * gi : gi];  // low word: sign-safe
            }
            float4 v = make_float4(0.f, 0.f, 0.f, 0.f);
            if (idx >= 0 && idx < H_) v = g_xT4[(size_t)idx * 4 + q];
            float* p = dst + (4 * q) * PITCH + r;
            p[0 * PITCH] = v.x;
            p[1 * PITCH] = v.y;
            p[2 * PITCH] = v.z;
            p[3 * PITCH] = v.w;
        }
    };

    gather(0, col);
    __syncthreads();

    unsigned long long acc[4][4];   // [o-pair][h]
#pragma unroll
    for (int a = 0; a < 4; a++)
#pragma unroll
        for (int b = 0; b < 4; b++) acc[a][b] = 0ull;

#pragma unroll 1
    for (int k = 0; k < KK; k++) {
        const float* cc = col + (k & 1) * COLSZ;
        float*       cn = col + ((k + 1) & 1) * COLSZ;
        if (k + 1 < KK) gather(k + 1, cn);

#pragma unroll
        for (int i = 0; i < CIN; i++) {
            float4 c4 = *reinterpret_cast<const float4*>(cc + i * PITCH + hg);
            unsigned long long cd[4] = {pack_dup(c4.x), pack_dup(c4.y),
                                        pack_dup(c4.z), pack_dup(c4.w)};
            // 8 weights for this warp: two uniform LDG.128 from repacked table
            const float4* wp4 =
                reinterpret_cast<const float4*>(g_wpk + (k * CIN + i) * COUT + og);
            float4 wa = __ldg(wp4);
            float4 wb = __ldg(wp4 + 1);
            unsigned long long w01 = pack2(wa.x, wa.y), w23 = pack2(wa.z, wa.w);
            unsigned long long w45 = pack2(wb.x, wb.y), w67 = pack2(wb.z, wb.w);
#pragma unroll
            for (int hh = 0; hh < 4; hh++) {
                acc[0][hh] = fma_f32x2(w01, cd[hh], acc[0][hh]);
                acc[1][hh] = fma_f32x2(w23, cd[hh], acc[1][hh]);
                acc[2][hh] = fma_f32x2(w45, cd[hh], acc[2][hh]);
                acc[3][hh] = fma_f32x2(w67, cd[hh], acc[3][hh]);
            }
        }
        __syncthreads();
    }

    // Unpack, write y (coalesced float4 per o), per-warp BN partials.
    const bool valid = (h0 + hg) < H_;   // quad-granular: H_ % 4 == 0
    float s[8], ss[8];
#pragma unroll
    for (int op = 0; op < 4; op++) {
        float lo[4], hi[4];
#pragma unroll
        for (int hh = 0; hh < 4; hh++) unpack2(acc[op][hh], lo[hh], hi[hh]);
        if (valid) {
            *reinterpret_cast<float4*>(out + (size_t)(og + 2 * op) * H_ + h0 + hg) =
                make_float4(lo[0], lo[1], lo[2], lo[3]);
            *reinterpret_cast<float4*>(out + (size_t)(og + 2 * op + 1) * H_ + h0 + hg) =
                make_float4(hi[0], hi[1], hi[2], hi[3]);
        }
        s[2 * op]      = lo[0] + lo[1] + lo[2] + lo[3];
        s[2 * op + 1]  = hi[0] + hi[1] + hi[2] + hi[3];
        ss[2 * op]     = lo[0] * lo[0] + lo[1] * lo[1] + lo[2] * lo[2] + lo[3] * lo[3];
        ss[2 * op + 1] = hi[0] * hi[0] + hi[1] * hi[1] + hi[2] * hi[2] + hi[3] * hi[3];
    }
#pragma unroll
    for (int oo = 0; oo < 8; oo++) {
        float v = s[oo], qv = ss[oo];
#pragma unroll
        for (int sft = 16; sft > 0; sft >>= 1) {
            v  += __shfl_down_sync(0xffffffffu, v, sft);
            qv += __shfl_down_sync(0xffffffffu, qv, sft);
        }
        if (lane == 0) {
            g_partials[(og + oo) * NBLK + blockIdx.x]      = v;
            g_partials[(32 + og + oo) * NBLK + blockIdx.x] = qv;
        }
    }
}

// ---------------------------------------------------------------------------
// Kernel 4: one block per channel; deterministic fp64 reduction -> scale/bias.
// ---------------------------------------------------------------------------
__global__ void stats_kernel(const float* __restrict__ gamma,
                             const float* __restrict__ beta) {
    const int o = blockIdx.x;
    double s1 = 0.0, s2 = 0.0;
    for (int b = threadIdx.x; b < NBLK; b += blockDim.x) {
        s1 += (double)g_partials[o * NBLK + b];
        s2 += (double)g_partials[(32 + o) * NBLK + b];
    }
    __shared__ double r1[256], r2[256];
    r1[threadIdx.x] = s1;
    r2[threadIdx.x] = s2;
    __syncthreads();
    for (int sft = 128; sft > 0; sft >>= 1) {
        if (threadIdx.x < sft) {
            r1[threadIdx.x] += r1[threadIdx.x + sft];
            r2[threadIdx.x] += r2[threadIdx.x + sft];
        }
        __syncthreads();
    }
    if (threadIdx.x == 0) {
        double mean = r1[0] / (double)H_;
        double var  = r2[0] / (double)H_ - mean * mean;
        float rstd  = rsqrtf((float)(var + 1e-5));
        float sc    = rstd * gamma[o];
        g_scale[o]  = sc;
        g_bias[o]   = beta[o] - (float)mean * sc;
    }
}

// ---------------------------------------------------------------------------
// Kernel 5: normalize in place (float4; H % 4 == 0).
// ---------------------------------------------------------------------------
__global__ void bn_kernel(float* __restrict__ out) {
    const int o = blockIdx.y;
    const int t = blockIdx.x * blockDim.x + threadIdx.x;
    const float sc = g_scale[o], bi = g_bias[o];
    float4* p = reinterpret_cast<float4*>(out + (size_t)o * H_);
    if (t < H_ / 4) {
        float4 v = p[t];
        v.x = v.x * sc + bi;
        v.y = v.y * sc + bi;
        v.z = v.z * sc + bi;
        v.w = v.w * sc + bi;
        p[t] = v;
    }
}

// ---------------------------------------------------------------------------
extern "C" void kernel_launch(void* const* d_in, const int* in_sizes, int n_in,
                              void* d_out, int out_size) {
    const float* x     = (const float*)d_in[0];  // (1,16,300000,1)
    const float* w     = (const float*)d_in[1];  // (32,16,27)
    const float* gamma = (const float*)d_in[2];  // (32,)
    const float* beta  = (const float*)d_in[3];  // (32,)
    const void*  neigh = d_in[4];                // (300000,27) i64 or i32
    float*       out   = (float*)d_out;          // (1,32,300000,1)

    detect_kernel<<<1, 1024>>>((const unsigned int*)neigh);
    repack_w_kernel<<<(WSZ + 255) / 256, 256>>>(w);
    transpose_x_kernel<<<(H_ + 255) / 256, 256>>>(x);
    conv_kernel<<<NBLK, TB>>>((const int*)neigh, out);
    stats_kernel<<<COUT, 256>>>(gamma, beta);
    bn_kernel<<<dim3((H_ / 4 + 255) / 256, COUT), 256>>>(out);
}